// round 1
// baseline (speedup 1.0000x reference)
#include <cuda_runtime.h>
#include <math.h>
#include <stdint.h>

#define S_LEN 2048
#define HID   3584
#define NH    28
#define NKV   4
#define HD    128
#define KV_DIM 512   // NKV*HD

// Scratch (allocation-free rule: __device__ globals)
__device__ float g_Q[S_LEN * HID];     // (S, 28*128)
__device__ float g_K[S_LEN * KV_DIM];  // (S, 4*128)
__device__ float g_V[S_LEN * KV_DIM];
__device__ float g_A[S_LEN * HID];     // attention output before Wo

// ---------------------------------------------------------------------------
// Generic 128x128x16 SGEMM tile body. 256 threads, 8x8 register tile.
// A: row-major [M x Kdim], B: row-major [Kdim x ldb], C: row-major [M x ldb].
// All dims multiples of 128 / 16 (true for this problem). No edge guards.
// ---------------------------------------------------------------------------
__device__ __forceinline__ void sgemm_tile(
    const float* __restrict__ A, const float* __restrict__ B,
    float* __restrict__ C, int Kdim, int ldb, int bm, int bn)
{
    __shared__ float As[16][128];   // transposed: As[k][row]
    __shared__ float Bs[16][128];   // natural:    Bs[k][col]

    const int tid = threadIdx.x;
    const int tm = tid >> 4;        // 0..15 (row group)
    const int tn = tid & 15;        // 0..15 (col group)

    float acc[8][8];
#pragma unroll
    for (int i = 0; i < 8; ++i)
#pragma unroll
        for (int j = 0; j < 8; ++j) acc[i][j] = 0.f;

    for (int kt = 0; kt < Kdim; kt += 16) {
#pragma unroll
        for (int l = 0; l < 2; ++l) {
            int f = (l << 8) + tid;          // 0..511
            // A tile: 128 rows x 16 k  (512 float4)
            int r  = f >> 2;
            int k4 = (f & 3) << 2;
            float4 a = *(const float4*)(A + (size_t)(bm + r) * Kdim + kt + k4);
            As[k4 + 0][r] = a.x; As[k4 + 1][r] = a.y;
            As[k4 + 2][r] = a.z; As[k4 + 3][r] = a.w;
            // B tile: 16 k x 128 cols (512 float4)
            int kr = f >> 5;
            int c4 = (f & 31) << 2;
            *(float4*)&Bs[kr][c4] =
                *(const float4*)(B + (size_t)(kt + kr) * ldb + bn + c4);
        }
        __syncthreads();

#pragma unroll
        for (int k = 0; k < 16; ++k) {
            float a[8], b[8];
            *(float4*)(a)     = *(const float4*)&As[k][tm * 8];
            *(float4*)(a + 4) = *(const float4*)&As[k][tm * 8 + 4];
            *(float4*)(b)     = *(const float4*)&Bs[k][tn * 8];
            *(float4*)(b + 4) = *(const float4*)&Bs[k][tn * 8 + 4];
#pragma unroll
            for (int i = 0; i < 8; ++i)
#pragma unroll
                for (int j = 0; j < 8; ++j)
                    acc[i][j] = fmaf(a[i], b[j], acc[i][j]);
        }
        __syncthreads();
    }

#pragma unroll
    for (int i = 0; i < 8; ++i) {
        float* cp = C + (size_t)(bm + tm * 8 + i) * ldb + bn + tn * 8;
        float4 c0 = {acc[i][0], acc[i][1], acc[i][2], acc[i][3]};
        float4 c1 = {acc[i][4], acc[i][5], acc[i][6], acc[i][7]};
        *(float4*)cp       = c0;
        *(float4*)(cp + 4) = c1;
    }
}

// Fused QKV projection: grid.x = 36 column blocks (28 Q + 4 K + 4 V), grid.y = 16 row blocks
__global__ __launch_bounds__(256) void qkv_kernel(
    const float* __restrict__ X, const float* __restrict__ Wq,
    const float* __restrict__ Wk, const float* __restrict__ Wv)
{
    int nb = blockIdx.x;
    const float* B; float* C; int ldb, bn;
    if (nb < 28)       { B = Wq; C = g_Q; ldb = HID;    bn = nb * 128; }
    else if (nb < 32)  { B = Wk; C = g_K; ldb = KV_DIM; bn = (nb - 28) * 128; }
    else               { B = Wv; C = g_V; ldb = KV_DIM; bn = (nb - 32) * 128; }
    sgemm_tile(X, B, C, HID, ldb, blockIdx.y * 128, bn);
}

// Output projection: out = g_A @ Wo
__global__ __launch_bounds__(256) void out_proj_kernel(
    const float* __restrict__ Wo, float* __restrict__ out)
{
    sgemm_tile(g_A, Wo, out, HID, HID, blockIdx.y * 128, blockIdx.x * 128);
}

// ---------------------------------------------------------------------------
// RoPE applied in-place to Q (28 heads) and K (4 heads).
// One thread per (s, head, pair-index i in [0,64)).
// ---------------------------------------------------------------------------
__global__ void rope_kernel(const int* __restrict__ pos_ids)
{
    int idx = blockIdx.x * blockDim.x + threadIdx.x;
    if (idx >= S_LEN * (NH + NKV) * 64) return;
    int i  = idx & 63;
    int t  = idx >> 6;
    int hh = t & 31;          // 32 total heads (28 Q + 4 K)
    int s  = t >> 5;

    // inv_freq = theta^(-i/64), ln(1e6)/64 = 0.21586735246819178
    float inv_freq = expf(-(float)i * 0.21586735246819178f);
    float ang = (float)pos_ids[s] * inv_freq;
    float sv, cv;
    sincosf(ang, &sv, &cv);

    float* p;
    if (hh < NH) p = g_Q + (size_t)s * HID    + hh * 128;
    else         p = g_K + (size_t)s * KV_DIM + (hh - NH) * 128;
    float x0 = p[i], x1 = p[i + 64];
    p[i]      = x0 * cv - x1 * sv;
    p[i + 64] = x1 * cv + x0 * sv;
}

// ---------------------------------------------------------------------------
// Causal flash attention (fp32 SIMT). Grid: (32 q-tiles, 28 heads), 128 threads.
// BM=BN=64, D=128. m/l kept in registers, replicated across each 8-lane row group.
// ---------------------------------------------------------------------------
#define QS_STRIDE 129
#define PS_STRIDE 68
#define FLASH_SMEM_FLOATS (64*QS_STRIDE + 64*QS_STRIDE + 64*128 + 64*PS_STRIDE)

__global__ __launch_bounds__(128) void flash_kernel()
{
    const int qt = blockIdx.x;
    const int h  = blockIdx.y;
    const int kvh = h / (NH / NKV);

    extern __shared__ float smf[];
    float* Qs = smf;                       // [64][129]
    float* Ks = Qs + 64 * QS_STRIDE;       // [64][129]
    float* Vs = Ks + 64 * QS_STRIDE;       // [64][128]
    float* Ps = Vs + 64 * 128;             // [64][68]

    const int tid = threadIdx.x;
    const int tm = tid >> 3;   // 0..15 -> rows tm*4..tm*4+3
    const int tn = tid & 7;    // 0..7

    // Load Q tile (64 x 128) into padded smem
    for (int f = tid; f < 2048; f += 128) {
        int r = f >> 5, c4 = (f & 31) << 2;
        float4 q4 = *(const float4*)&g_Q[(size_t)(qt * 64 + r) * HID + h * 128 + c4];
        float* d = &Qs[r * QS_STRIDE + c4];
        d[0] = q4.x; d[1] = q4.y; d[2] = q4.z; d[3] = q4.w;
    }

    float m[4], l[4], o[4][16];
#pragma unroll
    for (int i = 0; i < 4; ++i) {
        m[i] = -INFINITY; l[i] = 0.f;
#pragma unroll
        for (int c = 0; c < 16; ++c) o[i][c] = 0.f;
    }
    const float scale = 0.08838834764831845f;  // 1/sqrt(128)

    for (int kt = 0; kt <= qt; ++kt) {
        __syncthreads();   // prior iteration done reading Ks/Vs/Ps
        for (int f = tid; f < 2048; f += 128) {
            int r = f >> 5, c4 = (f & 31) << 2;
            size_t g = (size_t)(kt * 64 + r) * KV_DIM + kvh * 128 + c4;
            float4 k4 = *(const float4*)&g_K[g];
            float* d = &Ks[r * QS_STRIDE + c4];
            d[0] = k4.x; d[1] = k4.y; d[2] = k4.z; d[3] = k4.w;
            *(float4*)&Vs[r * 128 + c4] = *(const float4*)&g_V[g];
        }
        __syncthreads();

        // S = Q @ K^T : thread tile 4 rows x 8 cols
        float acc[4][8];
#pragma unroll
        for (int i = 0; i < 4; ++i)
#pragma unroll
            for (int j = 0; j < 8; ++j) acc[i][j] = 0.f;

#pragma unroll 8
        for (int k = 0; k < 128; ++k) {
            float a[4], b[8];
#pragma unroll
            for (int i = 0; i < 4; ++i) a[i] = Qs[(tm * 4 + i) * QS_STRIDE + k];
#pragma unroll
            for (int j = 0; j < 8; ++j) b[j] = Ks[(tn * 8 + j) * QS_STRIDE + k];
#pragma unroll
            for (int i = 0; i < 4; ++i)
#pragma unroll
                for (int j = 0; j < 8; ++j)
                    acc[i][j] = fmaf(a[i], b[j], acc[i][j]);
        }

        // Online softmax (causal mask); row stats replicated across 8-lane group
        const int qi0 = qt * 64 + tm * 4;
        const int kj0 = kt * 64 + tn * 8;
        float alpha[4];
#pragma unroll
        for (int i = 0; i < 4; ++i) {
            float mx = -INFINITY;
#pragma unroll
            for (int j = 0; j < 8; ++j) {
                float s = acc[i][j] * scale;
                if (kj0 + j > qi0 + i) s = -INFINITY;
                acc[i][j] = s;
                mx = fmaxf(mx, s);
            }
            mx = fmaxf(mx, __shfl_xor_sync(0xffffffffu, mx, 1));
            mx = fmaxf(mx, __shfl_xor_sync(0xffffffffu, mx, 2));
            mx = fmaxf(mx, __shfl_xor_sync(0xffffffffu, mx, 4));
            float mnew = fmaxf(m[i], mx);
            float al = __expf(m[i] - mnew);
            float ls = 0.f;
#pragma unroll
            for (int j = 0; j < 8; ++j) {
                float p = __expf(acc[i][j] - mnew);
                Ps[(tm * 4 + i) * PS_STRIDE + tn * 8 + j] = p;
                ls += p;
            }
            ls += __shfl_xor_sync(0xffffffffu, ls, 1);
            ls += __shfl_xor_sync(0xffffffffu, ls, 2);
            ls += __shfl_xor_sync(0xffffffffu, ls, 4);
            l[i] = l[i] * al + ls;
            m[i] = mnew;
            alpha[i] = al;
        }
        __syncthreads();   // Ps ready for all threads

        // O = O*alpha + P @ V : thread tile 4 rows x 16 cols
#pragma unroll
        for (int i = 0; i < 4; ++i)
#pragma unroll
            for (int c = 0; c < 16; ++c) o[i][c] *= alpha[i];

#pragma unroll 4
        for (int k = 0; k < 64; ++k) {
            float a[4];
#pragma unroll
            for (int i = 0; i < 4; ++i) a[i] = Ps[(tm * 4 + i) * PS_STRIDE + k];
            float4 v0 = *(const float4*)&Vs[k * 128 + tn * 16];
            float4 v1 = *(const float4*)&Vs[k * 128 + tn * 16 + 4];
            float4 v2 = *(const float4*)&Vs[k * 128 + tn * 16 + 8];
            float4 v3 = *(const float4*)&Vs[k * 128 + tn * 16 + 12];
#pragma unroll
            for (int i = 0; i < 4; ++i) {
                o[i][0]  = fmaf(a[i], v0.x, o[i][0]);
                o[i][1]  = fmaf(a[i], v0.y, o[i][1]);
                o[i][2]  = fmaf(a[i], v0.z, o[i][2]);
                o[i][3]  = fmaf(a[i], v0.w, o[i][3]);
                o[i][4]  = fmaf(a[i], v1.x, o[i][4]);
                o[i][5]  = fmaf(a[i], v1.y, o[i][5]);
                o[i][6]  = fmaf(a[i], v1.z, o[i][6]);
                o[i][7]  = fmaf(a[i], v1.w, o[i][7]);
                o[i][8]  = fmaf(a[i], v2.x, o[i][8]);
                o[i][9]  = fmaf(a[i], v2.y, o[i][9]);
                o[i][10] = fmaf(a[i], v2.z, o[i][10]);
                o[i][11] = fmaf(a[i], v2.w, o[i][11]);
                o[i][12] = fmaf(a[i], v3.x, o[i][12]);
                o[i][13] = fmaf(a[i], v3.y, o[i][13]);
                o[i][14] = fmaf(a[i], v3.z, o[i][14]);
                o[i][15] = fmaf(a[i], v3.w, o[i][15]);
            }
        }
    }

    // Normalize and write to g_A (S, H) layout
#pragma unroll
    for (int i = 0; i < 4; ++i) {
        float inv = 1.0f / l[i];
        float* op = &g_A[(size_t)(qt * 64 + tm * 4 + i) * HID + h * 128 + tn * 16];
        float4 r0 = {o[i][0] * inv,  o[i][1] * inv,  o[i][2] * inv,  o[i][3] * inv};
        float4 r1 = {o[i][4] * inv,  o[i][5] * inv,  o[i][6] * inv,  o[i][7] * inv};
        float4 r2 = {o[i][8] * inv,  o[i][9] * inv,  o[i][10] * inv, o[i][11] * inv};
        float4 r3 = {o[i][12] * inv, o[i][13] * inv, o[i][14] * inv, o[i][15] * inv};
        *(float4*)(op)      = r0;
        *(float4*)(op + 4)  = r1;
        *(float4*)(op + 8)  = r2;
        *(float4*)(op + 12) = r3;
    }
}

// ---------------------------------------------------------------------------
extern "C" void kernel_launch(void* const* d_in, const int* in_sizes, int n_in,
                              void* d_out, int out_size)
{
    const float* X   = (const float*)d_in[0];   // hidden_states (1,2048,3584)
    const int*   pid = (const int*)  d_in[1];   // position_ids (1,2048)
    const float* Wq  = (const float*)d_in[2];
    const float* Wk  = (const float*)d_in[3];
    const float* Wv  = (const float*)d_in[4];
    const float* Wo  = (const float*)d_in[5];
    float* out = (float*)d_out;

    // QKV projections (fused column blocks: 28 Q + 4 K + 4 V)
    qkv_kernel<<<dim3(36, 16), 256>>>(X, Wq, Wk, Wv);

    // RoPE on Q and K
    rope_kernel<<<(S_LEN * 32 * 64 + 255) / 256, 256>>>(pid);

    // Flash attention
    static int smem_set = 0;
    int flash_smem = FLASH_SMEM_FLOATS * (int)sizeof(float);
    if (!smem_set) {
        cudaFuncSetAttribute(flash_kernel,
                             cudaFuncAttributeMaxDynamicSharedMemorySize,
                             flash_smem);
        smem_set = 1;
    }
    flash_kernel<<<dim3(32, 28), 128, flash_smem>>>();

    // Output projection
    out_proj_kernel<<<dim3(28, 16), 256>>>(Wo, out);
}

// round 3
// speedup vs baseline: 1.5054x; 1.5054x over previous
#include <cuda_runtime.h>
#include <cuda_bf16.h>
#include <math.h>
#include <stdint.h>

#define S_LEN 2048
#define HID   3584
#define NH    28
#define NKV   4
#define HD    128
#define KV_DIM 512
#define QKV_N  4608   // 3584 + 512 + 512

// ---------------- scratch (__device__ globals; no allocs allowed) ----------
__device__ float g_Q[S_LEN * HID];
__device__ float g_K[S_LEN * KV_DIM];
__device__ float g_V[S_LEN * KV_DIM];
__device__ float g_A[S_LEN * HID];

__device__ __nv_bfloat16 g_Xhi[S_LEN * HID];
__device__ __nv_bfloat16 g_Xlo[S_LEN * HID];
__device__ __nv_bfloat16 g_Ahi[S_LEN * HID];
__device__ __nv_bfloat16 g_Alo[S_LEN * HID];
__device__ __nv_bfloat16 g_Wt_hi[(size_t)QKV_N * HID];  // [n][k] QKV weights
__device__ __nv_bfloat16 g_Wt_lo[(size_t)QKV_N * HID];
__device__ __nv_bfloat16 g_Wo_hi[(size_t)HID * HID];    // [n][k] Wo
__device__ __nv_bfloat16 g_Wo_lo[(size_t)HID * HID];

// ---------------- PTX helpers (baseline PTX only; no sm_103a features) -----
__device__ __forceinline__ uint32_t smem_u32(const void* p) {
    uint32_t a;
    asm("{ .reg .u64 t; cvta.to.shared.u64 t, %1; cvt.u32.u64 %0, t; }" : "=r"(a) : "l"(p));
    return a;
}
__device__ __forceinline__ void cp_async16(uint32_t dst, const void* src) {
    asm volatile("cp.async.cg.shared.global [%0], [%1], 16;" :: "r"(dst), "l"(src));
}
#define CP_COMMIT() asm volatile("cp.async.commit_group;" ::: "memory")
#define CP_WAIT(N)  asm volatile("cp.async.wait_group %0;" :: "n"(N) : "memory")

__device__ __forceinline__ void ldm4(uint32_t* r, uint32_t addr) {
    asm volatile("ldmatrix.sync.aligned.m8n8.x4.shared.b16 {%0,%1,%2,%3}, [%4];"
        : "=r"(r[0]), "=r"(r[1]), "=r"(r[2]), "=r"(r[3]) : "r"(addr));
}
__device__ __forceinline__ void mma16816(float* c, const uint32_t* a, const uint32_t* b) {
    asm volatile("mma.sync.aligned.m16n8k16.row.col.f32.bf16.bf16.f32 "
        "{%0,%1,%2,%3}, {%4,%5,%6,%7}, {%8,%9}, {%0,%1,%2,%3};"
        : "+f"(c[0]), "+f"(c[1]), "+f"(c[2]), "+f"(c[3])
        : "r"(a[0]), "r"(a[1]), "r"(a[2]), "r"(a[3]), "r"(b[0]), "r"(b[1]));
}

// ---------------- pre-processing kernels ------------------------------------
__global__ void split_x_kernel(const float* __restrict__ X) {
    int i = blockIdx.x * blockDim.x + threadIdx.x;
    if (i < S_LEN * HID) {
        float x = X[i];
        __nv_bfloat16 h = __float2bfloat16(x);
        g_Xhi[i] = h;
        g_Xlo[i] = __float2bfloat16(x - __bfloat162float(h));
    }
}
__global__ void split_a_kernel() {
    int i = blockIdx.x * blockDim.x + threadIdx.x;
    if (i < S_LEN * HID) {
        float x = g_A[i];
        __nv_bfloat16 h = __float2bfloat16(x);
        g_Ahi[i] = h;
        g_Alo[i] = __float2bfloat16(x - __bfloat162float(h));
    }
}

// W[K][N] fp32 -> dst[n][k] bf16 hi/lo.  dstSel 0 -> g_Wt, 1 -> g_Wo.
__global__ void transpose_split(const float* __restrict__ W, int K, int N,
                                int dstSel, size_t dstOff) {
    __nv_bfloat16* Th = (dstSel ? g_Wo_hi : g_Wt_hi) + dstOff;
    __nv_bfloat16* Tl = (dstSel ? g_Wo_lo : g_Wt_lo) + dstOff;
    __shared__ float t[32][33];
    int n0 = blockIdx.x * 32, k0 = blockIdx.y * 32;
    int tx = threadIdx.x, ty = threadIdx.y;
#pragma unroll
    for (int i = 0; i < 32; i += 8)
        t[ty + i][tx] = W[(size_t)(k0 + ty + i) * N + n0 + tx];
    __syncthreads();
#pragma unroll
    for (int i = 0; i < 32; i += 8) {
        int n = n0 + ty + i, k = k0 + tx;
        float x = t[tx][ty + i];
        __nv_bfloat16 h = __float2bfloat16(x);
        Th[(size_t)n * K + k] = h;
        Tl[(size_t)n * K + k] = __float2bfloat16(x - __bfloat162float(h));
    }
}

// ---------------- HMMA bf16x3 GEMM ------------------------------------------
// C[128 x 128] tile = A[bm:bm+128, :K] @ B[bn:bn+128, :K]^T
// A, B given as bf16 hi/lo row-major [*, K]. fp32 accumulate.
#define BK 32
#define TSTRIDE 40                       // bf16 elems per smem row (pad 64B->80B)
#define TILE_BYTES (128 * TSTRIDE * 2)   // 10240
#define STAGE_BYTES (4 * TILE_BYTES)     // Ah | Al | Bh | Bl
#define GEMM_SMEM (2 * STAGE_BYTES)      // 81920

__device__ __forceinline__ void gemm_tile(
    const __nv_bfloat16* __restrict__ Ah, const __nv_bfloat16* __restrict__ Al,
    const __nv_bfloat16* __restrict__ Bh, const __nv_bfloat16* __restrict__ Bl,
    int Kd, int bm, int bnB, float* __restrict__ C, int ldc, int bnC)
{
    extern __shared__ char smem[];
    const uint32_t sbase = smem_u32(smem);
    const int tid  = threadIdx.x;
    const int wid  = tid >> 5;
    const int lane = tid & 31;
    const int nch  = Kd >> 5;            // BK = 32

    const int mbase = (wid >> 1) * 32;   // warp rows within tile
    const int nbase = (wid & 1) * 64;    // warp cols within tile

    // ldmatrix per-lane addressing components
    const int rowA = mbase + (lane & 15);
    const int colA = (lane >> 4) << 3;
    const int rowB = nbase + (lane & 7) + ((lane >> 4) << 3);
    const int colB = ((lane >> 3) & 1) << 3;

    float acc[2][8][4];
#pragma unroll
    for (int mt = 0; mt < 2; ++mt)
#pragma unroll
        for (int nb = 0; nb < 8; ++nb)
#pragma unroll
            for (int q = 0; q < 4; ++q) acc[mt][nb][q] = 0.f;

    // ---- stage loader: 2048 x 16B cp.async ----
    auto load_stage = [&](int ci, int buf) {
        const int k0 = ci << 5;
        const uint32_t st = sbase + buf * STAGE_BYTES;
#pragma unroll
        for (int it = 0; it < 8; ++it) {
            int u = tid + it * 256;
            int mat = u >> 9;            // 0 Ah, 1 Al, 2 Bh, 3 Bl
            int v = u & 511;
            int row = v >> 2;
            int seg = v & 3;             // 16B segment (8 bf16)
            const __nv_bfloat16* src;
            if (mat == 0)      src = Ah + (size_t)(bm + row) * Kd + k0 + seg * 8;
            else if (mat == 1) src = Al + (size_t)(bm + row) * Kd + k0 + seg * 8;
            else if (mat == 2) src = Bh + (size_t)(bnB + row) * Kd + k0 + seg * 8;
            else               src = Bl + (size_t)(bnB + row) * Kd + k0 + seg * 8;
            cp_async16(st + mat * TILE_BYTES + row * (TSTRIDE * 2) + seg * 16, src);
        }
        CP_COMMIT();
    };

    load_stage(0, 0);

    for (int i = 0; i < nch; ++i) {
        const int b = i & 1;
        if (i + 1 < nch) {
            load_stage(i + 1, b ^ 1);
            CP_WAIT(1);
        } else {
            CP_WAIT(0);
        }
        __syncthreads();

        const uint32_t sb = sbase + b * STAGE_BYTES;
#pragma unroll
        for (int kk = 0; kk < BK; kk += 16) {
            uint32_t fAh[2][4], fAl[2][4], fBh[4][4], fBl[4][4];
#pragma unroll
            for (int mt = 0; mt < 2; ++mt) {
                uint32_t ra = sb + ((rowA + mt * 16) * TSTRIDE + kk + colA) * 2;
                ldm4(fAh[mt], ra);
                ldm4(fAl[mt], ra + TILE_BYTES);
            }
#pragma unroll
            for (int jp = 0; jp < 4; ++jp) {
                uint32_t rb = sb + 2 * TILE_BYTES +
                              ((rowB + jp * 16) * TSTRIDE + kk + colB) * 2;
                ldm4(fBh[jp], rb);
                ldm4(fBl[jp], rb + TILE_BYTES);
            }
#pragma unroll
            for (int mt = 0; mt < 2; ++mt)
#pragma unroll
                for (int nb = 0; nb < 8; ++nb) {
                    const uint32_t* bh = &fBh[nb >> 1][(nb & 1) * 2];
                    const uint32_t* bl = &fBl[nb >> 1][(nb & 1) * 2];
                    mma16816(acc[mt][nb], fAh[mt], bh);
                    mma16816(acc[mt][nb], fAh[mt], bl);
                    mma16816(acc[mt][nb], fAl[mt], bh);
                }
        }
        __syncthreads();
    }

    // ---- epilogue: fragment regs -> global fp32 ----
#pragma unroll
    for (int mt = 0; mt < 2; ++mt)
#pragma unroll
        for (int nb = 0; nb < 8; ++nb) {
            int r0 = bm + mbase + mt * 16 + (lane >> 2);
            int c0 = bnC + nbase + nb * 8 + (lane & 3) * 2;
            float2 v0 = {acc[mt][nb][0], acc[mt][nb][1]};
            float2 v1 = {acc[mt][nb][2], acc[mt][nb][3]};
            *(float2*)(C + (size_t)r0 * ldc + c0)       = v0;
            *(float2*)(C + (size_t)(r0 + 8) * ldc + c0) = v1;
        }
}

__global__ __launch_bounds__(256) void qkv_gemm_kernel() {
    int bn = blockIdx.x * 128;
    int bm = blockIdx.y * 128;
    float* C; int ldc, cn;
    if (bn < HID)            { C = g_Q; ldc = HID;    cn = bn; }
    else if (bn < HID + 512) { C = g_K; ldc = KV_DIM; cn = bn - HID; }
    else                     { C = g_V; ldc = KV_DIM; cn = bn - HID - 512; }
    gemm_tile(g_Xhi, g_Xlo, g_Wt_hi, g_Wt_lo, HID, bm, bn, C, ldc, cn);
}

__global__ __launch_bounds__(256) void out_gemm_kernel(float* __restrict__ out) {
    gemm_tile(g_Ahi, g_Alo, g_Wo_hi, g_Wo_lo, HID,
              blockIdx.y * 128, blockIdx.x * 128, out, HID, blockIdx.x * 128);
}

// ---------------- RoPE ------------------------------------------------------
__global__ void rope_kernel(const int* __restrict__ pos_ids)
{
    int idx = blockIdx.x * blockDim.x + threadIdx.x;
    if (idx >= S_LEN * (NH + NKV) * 64) return;
    int i  = idx & 63;
    int t  = idx >> 6;
    int hh = t & 31;
    int s  = t >> 5;

    float inv_freq = expf(-(float)i * 0.21586735246819178f);
    float ang = (float)pos_ids[s] * inv_freq;
    float sv, cv;
    sincosf(ang, &sv, &cv);

    float* p;
    if (hh < NH) p = g_Q + (size_t)s * HID    + hh * 128;
    else         p = g_K + (size_t)s * KV_DIM + (hh - NH) * 128;
    float x0 = p[i], x1 = p[i + 64];
    p[i]      = x0 * cv - x1 * sv;
    p[i + 64] = x1 * cv + x0 * sv;
}

// ---------------- flash attention (fp32 SIMT) -------------------------------
#define QS_STRIDE 129
#define PS_STRIDE 68
#define FLASH_SMEM_FLOATS (64*QS_STRIDE + 64*QS_STRIDE + 64*128 + 64*PS_STRIDE)

__global__ __launch_bounds__(128) void flash_kernel()
{
    const int qt = blockIdx.x;
    const int h  = blockIdx.y;
    const int kvh = h / (NH / NKV);

    extern __shared__ float smf[];
    float* Qs = smf;
    float* Ks = Qs + 64 * QS_STRIDE;
    float* Vs = Ks + 64 * QS_STRIDE;
    float* Ps = Vs + 64 * 128;

    const int tid = threadIdx.x;
    const int tm = tid >> 3;
    const int tn = tid & 7;

    for (int f = tid; f < 2048; f += 128) {
        int r = f >> 5, c4 = (f & 31) << 2;
        float4 q4 = *(const float4*)&g_Q[(size_t)(qt * 64 + r) * HID + h * 128 + c4];
        float* d = &Qs[r * QS_STRIDE + c4];
        d[0] = q4.x; d[1] = q4.y; d[2] = q4.z; d[3] = q4.w;
    }

    float m[4], l[4], o[4][16];
#pragma unroll
    for (int i = 0; i < 4; ++i) {
        m[i] = -INFINITY; l[i] = 0.f;
#pragma unroll
        for (int c = 0; c < 16; ++c) o[i][c] = 0.f;
    }
    const float scale = 0.08838834764831845f;

    for (int kt = 0; kt <= qt; ++kt) {
        __syncthreads();
        for (int f = tid; f < 2048; f += 128) {
            int r = f >> 5, c4 = (f & 31) << 2;
            size_t g = (size_t)(kt * 64 + r) * KV_DIM + kvh * 128 + c4;
            float4 k4 = *(const float4*)&g_K[g];
            float* d = &Ks[r * QS_STRIDE + c4];
            d[0] = k4.x; d[1] = k4.y; d[2] = k4.z; d[3] = k4.w;
            *(float4*)&Vs[r * 128 + c4] = *(const float4*)&g_V[g];
        }
        __syncthreads();

        float acc[4][8];
#pragma unroll
        for (int i = 0; i < 4; ++i)
#pragma unroll
            for (int j = 0; j < 8; ++j) acc[i][j] = 0.f;

#pragma unroll 8
        for (int k = 0; k < 128; ++k) {
            float a[4], b[8];
#pragma unroll
            for (int i = 0; i < 4; ++i) a[i] = Qs[(tm * 4 + i) * QS_STRIDE + k];
#pragma unroll
            for (int j = 0; j < 8; ++j) b[j] = Ks[(tn * 8 + j) * QS_STRIDE + k];
#pragma unroll
            for (int i = 0; i < 4; ++i)
#pragma unroll
                for (int j = 0; j < 8; ++j)
                    acc[i][j] = fmaf(a[i], b[j], acc[i][j]);
        }

        const int qi0 = qt * 64 + tm * 4;
        const int kj0 = kt * 64 + tn * 8;
        float alpha[4];
#pragma unroll
        for (int i = 0; i < 4; ++i) {
            float mx = -INFINITY;
#pragma unroll
            for (int j = 0; j < 8; ++j) {
                float s = acc[i][j] * scale;
                if (kj0 + j > qi0 + i) s = -INFINITY;
                acc[i][j] = s;
                mx = fmaxf(mx, s);
            }
            mx = fmaxf(mx, __shfl_xor_sync(0xffffffffu, mx, 1));
            mx = fmaxf(mx, __shfl_xor_sync(0xffffffffu, mx, 2));
            mx = fmaxf(mx, __shfl_xor_sync(0xffffffffu, mx, 4));
            float mnew = fmaxf(m[i], mx);
            float al = __expf(m[i] - mnew);
            float ls = 0.f;
#pragma unroll
            for (int j = 0; j < 8; ++j) {
                float p = __expf(acc[i][j] - mnew);
                Ps[(tm * 4 + i) * PS_STRIDE + tn * 8 + j] = p;
                ls += p;
            }
            ls += __shfl_xor_sync(0xffffffffu, ls, 1);
            ls += __shfl_xor_sync(0xffffffffu, ls, 2);
            ls += __shfl_xor_sync(0xffffffffu, ls, 4);
            l[i] = l[i] * al + ls;
            m[i] = mnew;
            alpha[i] = al;
        }
        __syncthreads();

#pragma unroll
        for (int i = 0; i < 4; ++i)
#pragma unroll
            for (int c = 0; c < 16; ++c) o[i][c] *= alpha[i];

#pragma unroll 4
        for (int k = 0; k < 64; ++k) {
            float a[4];
#pragma unroll
            for (int i = 0; i < 4; ++i) a[i] = Ps[(tm * 4 + i) * PS_STRIDE + k];
            float4 v0 = *(const float4*)&Vs[k * 128 + tn * 16];
            float4 v1 = *(const float4*)&Vs[k * 128 + tn * 16 + 4];
            float4 v2 = *(const float4*)&Vs[k * 128 + tn * 16 + 8];
            float4 v3 = *(const float4*)&Vs[k * 128 + tn * 16 + 12];
#pragma unroll
            for (int i = 0; i < 4; ++i) {
                o[i][0]  = fmaf(a[i], v0.x, o[i][0]);
                o[i][1]  = fmaf(a[i], v0.y, o[i][1]);
                o[i][2]  = fmaf(a[i], v0.z, o[i][2]);
                o[i][3]  = fmaf(a[i], v0.w, o[i][3]);
                o[i][4]  = fmaf(a[i], v1.x, o[i][4]);
                o[i][5]  = fmaf(a[i], v1.y, o[i][5]);
                o[i][6]  = fmaf(a[i], v1.z, o[i][6]);
                o[i][7]  = fmaf(a[i], v1.w, o[i][7]);
                o[i][8]  = fmaf(a[i], v2.x, o[i][8]);
                o[i][9]  = fmaf(a[i], v2.y, o[i][9]);
                o[i][10] = fmaf(a[i], v2.z, o[i][10]);
                o[i][11] = fmaf(a[i], v2.w, o[i][11]);
                o[i][12] = fmaf(a[i], v3.x, o[i][12]);
                o[i][13] = fmaf(a[i], v3.y, o[i][13]);
                o[i][14] = fmaf(a[i], v3.z, o[i][14]);
                o[i][15] = fmaf(a[i], v3.w, o[i][15]);
            }
        }
    }

#pragma unroll
    for (int i = 0; i < 4; ++i) {
        float inv = 1.0f / l[i];
        float* op = &g_A[(size_t)(qt * 64 + tm * 4 + i) * HID + h * 128 + tn * 16];
        float4 r0 = {o[i][0] * inv,  o[i][1] * inv,  o[i][2] * inv,  o[i][3] * inv};
        float4 r1 = {o[i][4] * inv,  o[i][5] * inv,  o[i][6] * inv,  o[i][7] * inv};
        float4 r2 = {o[i][8] * inv,  o[i][9] * inv,  o[i][10] * inv, o[i][11] * inv};
        float4 r3 = {o[i][12] * inv, o[i][13] * inv, o[i][14] * inv, o[i][15] * inv};
        *(float4*)(op)      = r0;
        *(float4*)(op + 4)  = r1;
        *(float4*)(op + 8)  = r2;
        *(float4*)(op + 12) = r3;
    }
}

// ---------------------------------------------------------------------------
extern "C" void kernel_launch(void* const* d_in, const int* in_sizes, int n_in,
                              void* d_out, int out_size)
{
    const float* X   = (const float*)d_in[0];
    const int*   pid = (const int*)  d_in[1];
    const float* Wq  = (const float*)d_in[2];
    const float* Wk  = (const float*)d_in[3];
    const float* Wv  = (const float*)d_in[4];
    const float* Wo  = (const float*)d_in[5];
    float* out = (float*)d_out;

    static int attr_set = 0;
    if (!attr_set) {
        cudaFuncSetAttribute(qkv_gemm_kernel, cudaFuncAttributeMaxDynamicSharedMemorySize, GEMM_SMEM);
        cudaFuncSetAttribute(out_gemm_kernel, cudaFuncAttributeMaxDynamicSharedMemorySize, GEMM_SMEM);
        cudaFuncSetAttribute(flash_kernel, cudaFuncAttributeMaxDynamicSharedMemorySize,
                             FLASH_SMEM_FLOATS * (int)sizeof(float));
        attr_set = 1;
    }

    // 1. split hidden_states into bf16 hi/lo
    split_x_kernel<<<(S_LEN * HID + 255) / 256, 256>>>(X);

    // 2. transpose + split weights into [n][k] bf16 hi/lo
    transpose_split<<<dim3(HID / 32, HID / 32), dim3(32, 8)>>>(Wq, HID, HID, 0, 0);
    transpose_split<<<dim3(KV_DIM / 32, HID / 32), dim3(32, 8)>>>(
        Wk, HID, KV_DIM, 0, (size_t)HID * HID);
    transpose_split<<<dim3(KV_DIM / 32, HID / 32), dim3(32, 8)>>>(
        Wv, HID, KV_DIM, 0, (size_t)(HID + 512) * HID);
    transpose_split<<<dim3(HID / 32, HID / 32), dim3(32, 8)>>>(Wo, HID, HID, 1, 0);

    // 3. QKV projections (HMMA bf16x3)
    qkv_gemm_kernel<<<dim3(QKV_N / 128, S_LEN / 128), 256, GEMM_SMEM>>>();

    // 4. RoPE
    rope_kernel<<<(S_LEN * 32 * 64 + 255) / 256, 256>>>(pid);

    // 5. flash attention (fp32)
    flash_kernel<<<dim3(32, 28), 128, FLASH_SMEM_FLOATS * (int)sizeof(float)>>>();

    // 6. split attention output
    split_a_kernel<<<(S_LEN * HID + 255) / 256, 256>>>();

    // 7. output projection (HMMA bf16x3)
    out_gemm_kernel<<<dim3(HID / 128, S_LEN / 128), 256, GEMM_SMEM>>>(out);
}

// round 4
// speedup vs baseline: 3.0222x; 2.0075x over previous
#include <cuda_runtime.h>
#include <cuda_bf16.h>
#include <math.h>
#include <stdint.h>

#define S_LEN 2048
#define HID   3584
#define NH    28
#define NKV   4
#define HD    128
#define KV_DIM 512
#define QKV_N  4608   // 3584 + 512 + 512

// ---------------- scratch (__device__ globals; no allocs allowed) ----------
__device__ float g_Q[S_LEN * HID];
__device__ float g_K[S_LEN * KV_DIM];
__device__ float g_V[S_LEN * KV_DIM];
__device__ float g_A[S_LEN * HID];

__device__ __nv_bfloat16 g_Xhi[S_LEN * HID];
__device__ __nv_bfloat16 g_Xlo[S_LEN * HID];
__device__ __nv_bfloat16 g_Ahi[S_LEN * HID];
__device__ __nv_bfloat16 g_Alo[S_LEN * HID];
__device__ __nv_bfloat16 g_Wt_hi[(size_t)QKV_N * HID];
__device__ __nv_bfloat16 g_Wt_lo[(size_t)QKV_N * HID];
__device__ __nv_bfloat16 g_Wo_hi[(size_t)HID * HID];
__device__ __nv_bfloat16 g_Wo_lo[(size_t)HID * HID];

// bf16 hi/lo of post-RoPE Q, K and of V (for HMMA flash)
__device__ __nv_bfloat16 g_Qh[S_LEN * HID];
__device__ __nv_bfloat16 g_Ql[S_LEN * HID];
__device__ __nv_bfloat16 g_Kh[S_LEN * KV_DIM];
__device__ __nv_bfloat16 g_Kl[S_LEN * KV_DIM];
__device__ __nv_bfloat16 g_Vh[S_LEN * KV_DIM];
__device__ __nv_bfloat16 g_Vl[S_LEN * KV_DIM];

// ---------------- PTX helpers (baseline PTX only) ---------------------------
__device__ __forceinline__ uint32_t smem_u32(const void* p) {
    uint32_t a;
    asm("{ .reg .u64 t; cvta.to.shared.u64 t, %1; cvt.u32.u64 %0, t; }" : "=r"(a) : "l"(p));
    return a;
}
__device__ __forceinline__ void cp_async16(uint32_t dst, const void* src) {
    asm volatile("cp.async.cg.shared.global [%0], [%1], 16;" :: "r"(dst), "l"(src));
}
#define CP_COMMIT() asm volatile("cp.async.commit_group;" ::: "memory")
#define CP_WAIT(N)  asm volatile("cp.async.wait_group %0;" :: "n"(N) : "memory")

__device__ __forceinline__ void ldm4(uint32_t* r, uint32_t addr) {
    asm volatile("ldmatrix.sync.aligned.m8n8.x4.shared.b16 {%0,%1,%2,%3}, [%4];"
        : "=r"(r[0]), "=r"(r[1]), "=r"(r[2]), "=r"(r[3]) : "r"(addr));
}
__device__ __forceinline__ void ldm4t(uint32_t* r, uint32_t addr) {
    asm volatile("ldmatrix.sync.aligned.m8n8.x4.trans.shared.b16 {%0,%1,%2,%3}, [%4];"
        : "=r"(r[0]), "=r"(r[1]), "=r"(r[2]), "=r"(r[3]) : "r"(addr));
}
__device__ __forceinline__ void mma16816(float* c, const uint32_t* a, const uint32_t* b) {
    asm volatile("mma.sync.aligned.m16n8k16.row.col.f32.bf16.bf16.f32 "
        "{%0,%1,%2,%3}, {%4,%5,%6,%7}, {%8,%9}, {%0,%1,%2,%3};"
        : "+f"(c[0]), "+f"(c[1]), "+f"(c[2]), "+f"(c[3])
        : "r"(a[0]), "r"(a[1]), "r"(a[2]), "r"(a[3]), "r"(b[0]), "r"(b[1]));
}
__device__ __forceinline__ uint32_t packbf2(float lo, float hi) {
    __nv_bfloat162 t = __floats2bfloat162_rn(lo, hi);   // t.x = lo (bits 0-15)
    return *(uint32_t*)&t;
}

// ---------------- pre-processing kernels ------------------------------------
__global__ void split_x_kernel(const float* __restrict__ X) {
    int i = blockIdx.x * blockDim.x + threadIdx.x;
    if (i < S_LEN * HID) {
        float x = X[i];
        __nv_bfloat16 h = __float2bfloat16(x);
        g_Xhi[i] = h;
        g_Xlo[i] = __float2bfloat16(x - __bfloat162float(h));
    }
}
__global__ void split_a_kernel() {
    int i = blockIdx.x * blockDim.x + threadIdx.x;
    if (i < S_LEN * HID) {
        float x = g_A[i];
        __nv_bfloat16 h = __float2bfloat16(x);
        g_Ahi[i] = h;
        g_Alo[i] = __float2bfloat16(x - __bfloat162float(h));
    }
}
// split post-RoPE Q, K and V into bf16 hi/lo
__global__ void qkv_split_kernel() {
    int i = blockIdx.x * blockDim.x + threadIdx.x;
    const int NQ = S_LEN * HID, NKVE = S_LEN * KV_DIM;
    if (i < NQ) {
        float x = g_Q[i];
        __nv_bfloat16 h = __float2bfloat16(x);
        g_Qh[i] = h;
        g_Ql[i] = __float2bfloat16(x - __bfloat162float(h));
    } else if (i < NQ + NKVE) {
        int j = i - NQ;
        float x = g_K[j];
        __nv_bfloat16 h = __float2bfloat16(x);
        g_Kh[j] = h;
        g_Kl[j] = __float2bfloat16(x - __bfloat162float(h));
    } else if (i < NQ + 2 * NKVE) {
        int j = i - NQ - NKVE;
        float x = g_V[j];
        __nv_bfloat16 h = __float2bfloat16(x);
        g_Vh[j] = h;
        g_Vl[j] = __float2bfloat16(x - __bfloat162float(h));
    }
}

// W[K][N] fp32 -> dst[n][k] bf16 hi/lo.
__global__ void transpose_split(const float* __restrict__ W, int K, int N,
                                int dstSel, size_t dstOff) {
    __nv_bfloat16* Th = (dstSel ? g_Wo_hi : g_Wt_hi) + dstOff;
    __nv_bfloat16* Tl = (dstSel ? g_Wo_lo : g_Wt_lo) + dstOff;
    __shared__ float t[32][33];
    int n0 = blockIdx.x * 32, k0 = blockIdx.y * 32;
    int tx = threadIdx.x, ty = threadIdx.y;
#pragma unroll
    for (int i = 0; i < 32; i += 8)
        t[ty + i][tx] = W[(size_t)(k0 + ty + i) * N + n0 + tx];
    __syncthreads();
#pragma unroll
    for (int i = 0; i < 32; i += 8) {
        int n = n0 + ty + i, k = k0 + tx;
        float x = t[tx][ty + i];
        __nv_bfloat16 h = __float2bfloat16(x);
        Th[(size_t)n * K + k] = h;
        Tl[(size_t)n * K + k] = __float2bfloat16(x - __bfloat162float(h));
    }
}

// ---------------- HMMA bf16x3 GEMM (unchanged from R3) -----------------------
#define BK 32
#define TSTRIDE 40
#define TILE_BYTES (128 * TSTRIDE * 2)
#define STAGE_BYTES (4 * TILE_BYTES)
#define GEMM_SMEM (2 * STAGE_BYTES)

__device__ __forceinline__ void gemm_tile(
    const __nv_bfloat16* __restrict__ Ah, const __nv_bfloat16* __restrict__ Al,
    const __nv_bfloat16* __restrict__ Bh, const __nv_bfloat16* __restrict__ Bl,
    int Kd, int bm, int bnB, float* __restrict__ C, int ldc, int bnC)
{
    extern __shared__ char smem[];
    const uint32_t sbase = smem_u32(smem);
    const int tid  = threadIdx.x;
    const int wid  = tid >> 5;
    const int lane = tid & 31;
    const int nch  = Kd >> 5;

    const int mbase = (wid >> 1) * 32;
    const int nbase = (wid & 1) * 64;

    const int rowA = mbase + (lane & 15);
    const int colA = (lane >> 4) << 3;
    const int rowB = nbase + (lane & 7) + ((lane >> 4) << 3);
    const int colB = ((lane >> 3) & 1) << 3;

    float acc[2][8][4];
#pragma unroll
    for (int mt = 0; mt < 2; ++mt)
#pragma unroll
        for (int nb = 0; nb < 8; ++nb)
#pragma unroll
            for (int q = 0; q < 4; ++q) acc[mt][nb][q] = 0.f;

    auto load_stage = [&](int ci, int buf) {
        const int k0 = ci << 5;
        const uint32_t st = sbase + buf * STAGE_BYTES;
#pragma unroll
        for (int it = 0; it < 8; ++it) {
            int u = tid + it * 256;
            int mat = u >> 9;
            int v = u & 511;
            int row = v >> 2;
            int seg = v & 3;
            const __nv_bfloat16* src;
            if (mat == 0)      src = Ah + (size_t)(bm + row) * Kd + k0 + seg * 8;
            else if (mat == 1) src = Al + (size_t)(bm + row) * Kd + k0 + seg * 8;
            else if (mat == 2) src = Bh + (size_t)(bnB + row) * Kd + k0 + seg * 8;
            else               src = Bl + (size_t)(bnB + row) * Kd + k0 + seg * 8;
            cp_async16(st + mat * TILE_BYTES + row * (TSTRIDE * 2) + seg * 16, src);
        }
        CP_COMMIT();
    };

    load_stage(0, 0);

    for (int i = 0; i < nch; ++i) {
        const int b = i & 1;
        if (i + 1 < nch) {
            load_stage(i + 1, b ^ 1);
            CP_WAIT(1);
        } else {
            CP_WAIT(0);
        }
        __syncthreads();

        const uint32_t sb = sbase + b * STAGE_BYTES;
#pragma unroll
        for (int kk = 0; kk < BK; kk += 16) {
            uint32_t fAh[2][4], fAl[2][4], fBh[4][4], fBl[4][4];
#pragma unroll
            for (int mt = 0; mt < 2; ++mt) {
                uint32_t ra = sb + ((rowA + mt * 16) * TSTRIDE + kk + colA) * 2;
                ldm4(fAh[mt], ra);
                ldm4(fAl[mt], ra + TILE_BYTES);
            }
#pragma unroll
            for (int jp = 0; jp < 4; ++jp) {
                uint32_t rb = sb + 2 * TILE_BYTES +
                              ((rowB + jp * 16) * TSTRIDE + kk + colB) * 2;
                ldm4(fBh[jp], rb);
                ldm4(fBl[jp], rb + TILE_BYTES);
            }
#pragma unroll
            for (int mt = 0; mt < 2; ++mt)
#pragma unroll
                for (int nb = 0; nb < 8; ++nb) {
                    const uint32_t* bh = &fBh[nb >> 1][(nb & 1) * 2];
                    const uint32_t* bl = &fBl[nb >> 1][(nb & 1) * 2];
                    mma16816(acc[mt][nb], fAh[mt], bh);
                    mma16816(acc[mt][nb], fAh[mt], bl);
                    mma16816(acc[mt][nb], fAl[mt], bh);
                }
        }
        __syncthreads();
    }

#pragma unroll
    for (int mt = 0; mt < 2; ++mt)
#pragma unroll
        for (int nb = 0; nb < 8; ++nb) {
            int r0 = bm + mbase + mt * 16 + (lane >> 2);
            int c0 = bnC + nbase + nb * 8 + (lane & 3) * 2;
            float2 v0 = {acc[mt][nb][0], acc[mt][nb][1]};
            float2 v1 = {acc[mt][nb][2], acc[mt][nb][3]};
            *(float2*)(C + (size_t)r0 * ldc + c0)       = v0;
            *(float2*)(C + (size_t)(r0 + 8) * ldc + c0) = v1;
        }
}

__global__ __launch_bounds__(256) void qkv_gemm_kernel() {
    int bn = blockIdx.x * 128;
    int bm = blockIdx.y * 128;
    float* C; int ldc, cn;
    if (bn < HID)            { C = g_Q; ldc = HID;    cn = bn; }
    else if (bn < HID + 512) { C = g_K; ldc = KV_DIM; cn = bn - HID; }
    else                     { C = g_V; ldc = KV_DIM; cn = bn - HID - 512; }
    gemm_tile(g_Xhi, g_Xlo, g_Wt_hi, g_Wt_lo, HID, bm, bn, C, ldc, cn);
}

__global__ __launch_bounds__(256) void out_gemm_kernel(float* __restrict__ out) {
    gemm_tile(g_Ahi, g_Alo, g_Wo_hi, g_Wo_lo, HID,
              blockIdx.y * 128, blockIdx.x * 128, out, HID, blockIdx.x * 128);
}

// ---------------- RoPE ------------------------------------------------------
__global__ void rope_kernel(const int* __restrict__ pos_ids)
{
    int idx = blockIdx.x * blockDim.x + threadIdx.x;
    if (idx >= S_LEN * (NH + NKV) * 64) return;
    int i  = idx & 63;
    int t  = idx >> 6;
    int hh = t & 31;
    int s  = t >> 5;

    float inv_freq = expf(-(float)i * 0.21586735246819178f);
    float ang = (float)pos_ids[s] * inv_freq;
    float sv, cv;
    sincosf(ang, &sv, &cv);

    float* p;
    if (hh < NH) p = g_Q + (size_t)s * HID    + hh * 128;
    else         p = g_K + (size_t)s * KV_DIM + (hh - NH) * 128;
    float x0 = p[i], x1 = p[i + 64];
    p[i]      = x0 * cv - x1 * sv;
    p[i + 64] = x1 * cv + x0 * sv;
}

// ---------------- HMMA bf16x3 flash attention --------------------------------
// CTA: 64 q rows (4 warps x 16), BN=64 kv tile, D=128.
// smem: 6 bf16 tiles [64][136] (Qh Ql Kh Kl Vh Vl), row stride 136 elems.
#define FS 136
#define F_QH 0
#define F_QL (64 * FS)
#define F_KH (2 * 64 * FS)
#define F_KL (3 * 64 * FS)
#define F_VH (4 * 64 * FS)
#define F_VL (5 * 64 * FS)
#define FLASH_SMEM (6 * 64 * FS * 2)     // 104448 bytes

__global__ __launch_bounds__(128) void flash_kernel()
{
    const int qt  = (int)gridDim.x - 1 - (int)blockIdx.x;   // heavy tiles first
    const int h   = blockIdx.y;
    const int kvh = h / (NH / NKV);

    extern __shared__ __nv_bfloat16 fsm[];
    const uint32_t sb = smem_u32(fsm);

    const int tid  = threadIdx.x;
    const int w    = tid >> 5;
    const int lane = tid & 31;

    // fragment addressing
    const int rowA   = w * 16 + (lane & 15);
    const int colA   = (lane >> 4) << 3;
    const int rowBo  = (lane & 7) + ((lane >> 4) << 3);
    const int colB   = ((lane >> 3) & 1) << 3;
    const int rowVt  = (lane & 7) + (((lane >> 3) & 1) << 3);
    const int colVt  = (lane >> 4) << 3;

    // load Q tile (hi/lo)
    for (int f = tid; f < 1024; f += 128) {
        int r = f >> 4, seg = f & 15;
        size_t g = (size_t)(qt * 64 + r) * HID + h * 128 + seg * 8;
        *(uint4*)&fsm[F_QH + r * FS + seg * 8] = *(const uint4*)&g_Qh[g];
        *(uint4*)&fsm[F_QL + r * FS + seg * 8] = *(const uint4*)&g_Ql[g];
    }

    float o[16][4];
#pragma unroll
    for (int nb = 0; nb < 16; ++nb)
#pragma unroll
        for (int q = 0; q < 4; ++q) o[nb][q] = 0.f;
    float m0 = -1e30f, m1 = -1e30f, l0 = 0.f, l1 = 0.f;

    const float SL = 0.08838834764831845f * 1.4426950408889634f; // scale*log2(e)

    for (int kt = 0; kt <= qt; ++kt) {
        __syncthreads();
        for (int f = tid; f < 1024; f += 128) {
            int r = f >> 4, seg = f & 15;
            size_t g = (size_t)(kt * 64 + r) * KV_DIM + kvh * 128 + seg * 8;
            *(uint4*)&fsm[F_KH + r * FS + seg * 8] = *(const uint4*)&g_Kh[g];
            *(uint4*)&fsm[F_KL + r * FS + seg * 8] = *(const uint4*)&g_Kl[g];
            *(uint4*)&fsm[F_VH + r * FS + seg * 8] = *(const uint4*)&g_Vh[g];
            *(uint4*)&fsm[F_VL + r * FS + seg * 8] = *(const uint4*)&g_Vl[g];
        }
        __syncthreads();

        // ---- S = Q K^T (bf16x3) ----
        float s[8][4];
#pragma unroll
        for (int nb = 0; nb < 8; ++nb)
#pragma unroll
            for (int q = 0; q < 4; ++q) s[nb][q] = 0.f;

#pragma unroll
        for (int ks = 0; ks < 8; ++ks) {
            uint32_t qh[4], ql[4];
            uint32_t ra = sb + (rowA * FS + ks * 16 + colA) * 2;
            ldm4(qh, ra + F_QH * 2);
            ldm4(ql, ra + F_QL * 2);
#pragma unroll
            for (int np = 0; np < 4; ++np) {
                uint32_t kh[4], kl[4];
                uint32_t rb = sb + ((np * 16 + rowBo) * FS + ks * 16 + colB) * 2;
                ldm4(kh, rb + F_KH * 2);
                ldm4(kl, rb + F_KL * 2);
#pragma unroll
                for (int half = 0; half < 2; ++half) {
                    int nb = np * 2 + half;
                    mma16816(s[nb], qh, &kh[half * 2]);
                    mma16816(s[nb], qh, &kl[half * 2]);
                    mma16816(s[nb], ql, &kh[half * 2]);
                }
            }
        }

        // ---- online softmax (exp2 domain) ----
        const bool diag = (kt == qt);
        const int rl0 = w * 16 + (lane >> 2);      // local row of c0,c1
        const int rl1 = rl0 + 8;
        float mx0 = -1e30f, mx1 = -1e30f;
#pragma unroll
        for (int nb = 0; nb < 8; ++nb) {
            int c0 = nb * 8 + (lane & 3) * 2;
#pragma unroll
            for (int q = 0; q < 4; ++q) {
                float v = s[nb][q] * SL;
                if (diag) {
                    int col = c0 + (q & 1);
                    int row = (q < 2) ? rl0 : rl1;
                    if (col > row) v = -1e30f;
                }
                s[nb][q] = v;
            }
            mx0 = fmaxf(mx0, fmaxf(s[nb][0], s[nb][1]));
            mx1 = fmaxf(mx1, fmaxf(s[nb][2], s[nb][3]));
        }
        mx0 = fmaxf(mx0, __shfl_xor_sync(0xffffffffu, mx0, 1));
        mx0 = fmaxf(mx0, __shfl_xor_sync(0xffffffffu, mx0, 2));
        mx1 = fmaxf(mx1, __shfl_xor_sync(0xffffffffu, mx1, 1));
        mx1 = fmaxf(mx1, __shfl_xor_sync(0xffffffffu, mx1, 2));

        float mn0 = fmaxf(m0, mx0), mn1 = fmaxf(m1, mx1);
        float a0 = exp2f(m0 - mn0), a1 = exp2f(m1 - mn1);
        float ls0 = 0.f, ls1 = 0.f;
#pragma unroll
        for (int nb = 0; nb < 8; ++nb) {
            float p0 = exp2f(s[nb][0] - mn0);
            float p1 = exp2f(s[nb][1] - mn0);
            float p2 = exp2f(s[nb][2] - mn1);
            float p3 = exp2f(s[nb][3] - mn1);
            s[nb][0] = p0; s[nb][1] = p1; s[nb][2] = p2; s[nb][3] = p3;
            ls0 += p0 + p1;
            ls1 += p2 + p3;
        }
        ls0 += __shfl_xor_sync(0xffffffffu, ls0, 1);
        ls0 += __shfl_xor_sync(0xffffffffu, ls0, 2);
        ls1 += __shfl_xor_sync(0xffffffffu, ls1, 1);
        ls1 += __shfl_xor_sync(0xffffffffu, ls1, 2);
        l0 = l0 * a0 + ls0;
        l1 = l1 * a1 + ls1;
        m0 = mn0; m1 = mn1;

#pragma unroll
        for (int nb = 0; nb < 16; ++nb) {
            o[nb][0] *= a0; o[nb][1] *= a0;
            o[nb][2] *= a1; o[nb][3] *= a1;
        }

        // ---- pack P into bf16 hi/lo A-fragments ----
        uint32_t pah[4][4], pal[4][4];
#pragma unroll
        for (int kb = 0; kb < 4; ++kb) {
#pragma unroll
            for (int part = 0; part < 4; ++part) {
                int nb = 2 * kb + (part >> 1);
                float c0 = s[nb][(part & 1) * 2];
                float c1 = s[nb][(part & 1) * 2 + 1];
                __nv_bfloat162 hi2 = __floats2bfloat162_rn(c0, c1);
                pah[kb][part] = *(uint32_t*)&hi2;
                float r0 = c0 - __bfloat162float(hi2.x);
                float r1 = c1 - __bfloat162float(hi2.y);
                pal[kb][part] = packbf2(r0, r1);
            }
        }

        // ---- O += P V (bf16x3) ----
#pragma unroll
        for (int kb = 0; kb < 4; ++kb) {
#pragma unroll
            for (int nv = 0; nv < 8; ++nv) {
                uint32_t vh[4], vl[4];
                uint32_t rv = sb + ((kb * 16 + rowVt) * FS + nv * 16 + colVt) * 2;
                ldm4t(vh, rv + F_VH * 2);
                ldm4t(vl, rv + F_VL * 2);
#pragma unroll
                for (int half = 0; half < 2; ++half) {
                    int nbv = nv * 2 + half;
                    mma16816(o[nbv], pah[kb], &vh[half * 2]);
                    mma16816(o[nbv], pal[kb], &vh[half * 2]);
                    mma16816(o[nbv], pah[kb], &vl[half * 2]);
                }
            }
        }
    }

    // ---- normalize + write to g_A ----
    const float inv0 = 1.0f / l0, inv1 = 1.0f / l1;
    const int r0 = qt * 64 + w * 16 + (lane >> 2);
    const int r1 = r0 + 8;
#pragma unroll
    for (int nb = 0; nb < 16; ++nb) {
        int c = h * 128 + nb * 8 + (lane & 3) * 2;
        float2 v0 = {o[nb][0] * inv0, o[nb][1] * inv0};
        float2 v1 = {o[nb][2] * inv1, o[nb][3] * inv1};
        *(float2*)&g_A[(size_t)r0 * HID + c] = v0;
        *(float2*)&g_A[(size_t)r1 * HID + c] = v1;
    }
}

// ---------------------------------------------------------------------------
extern "C" void kernel_launch(void* const* d_in, const int* in_sizes, int n_in,
                              void* d_out, int out_size)
{
    const float* X   = (const float*)d_in[0];
    const int*   pid = (const int*)  d_in[1];
    const float* Wq  = (const float*)d_in[2];
    const float* Wk  = (const float*)d_in[3];
    const float* Wv  = (const float*)d_in[4];
    const float* Wo  = (const float*)d_in[5];
    float* out = (float*)d_out;

    static int attr_set = 0;
    if (!attr_set) {
        cudaFuncSetAttribute(qkv_gemm_kernel, cudaFuncAttributeMaxDynamicSharedMemorySize, GEMM_SMEM);
        cudaFuncSetAttribute(out_gemm_kernel, cudaFuncAttributeMaxDynamicSharedMemorySize, GEMM_SMEM);
        cudaFuncSetAttribute(flash_kernel, cudaFuncAttributeMaxDynamicSharedMemorySize, FLASH_SMEM);
        attr_set = 1;
    }

    // 1. split hidden_states into bf16 hi/lo
    split_x_kernel<<<(S_LEN * HID + 255) / 256, 256>>>(X);

    // 2. transpose + split weights
    transpose_split<<<dim3(HID / 32, HID / 32), dim3(32, 8)>>>(Wq, HID, HID, 0, 0);
    transpose_split<<<dim3(KV_DIM / 32, HID / 32), dim3(32, 8)>>>(
        Wk, HID, KV_DIM, 0, (size_t)HID * HID);
    transpose_split<<<dim3(KV_DIM / 32, HID / 32), dim3(32, 8)>>>(
        Wv, HID, KV_DIM, 0, (size_t)(HID + 512) * HID);
    transpose_split<<<dim3(HID / 32, HID / 32), dim3(32, 8)>>>(Wo, HID, HID, 1, 0);

    // 3. QKV projections (HMMA bf16x3)
    qkv_gemm_kernel<<<dim3(QKV_N / 128, S_LEN / 128), 256, GEMM_SMEM>>>();

    // 4. RoPE (fp32, in place)
    rope_kernel<<<(S_LEN * 32 * 64 + 255) / 256, 256>>>(pid);

    // 5. split post-RoPE Q/K and V into bf16 hi/lo
    int nsplit = S_LEN * HID + 2 * S_LEN * KV_DIM;
    qkv_split_kernel<<<(nsplit + 255) / 256, 256>>>();

    // 6. flash attention (HMMA bf16x3)
    flash_kernel<<<dim3(32, 28), 128, FLASH_SMEM>>>();

    // 7. split attention output
    split_a_kernel<<<(S_LEN * HID + 255) / 256, 256>>>();

    // 8. output projection (HMMA bf16x3)
    out_gemm_kernel<<<dim3(HID / 128, S_LEN / 128), 256, GEMM_SMEM>>>(out);
}